// round 5
// baseline (speedup 1.0000x reference)
#include <cuda_runtime.h>
#include <math.h>

// predicts/targets (2,4,64,256,256) f32, masks (2,1,64,256,256) f32 -> scalar f32.
//
// Math identities (verified in R2):
//   omega_pred - omega_trgt = vorticity(scale*(P-T))  [linearity, shared mask]
//   scale 10 / (2*delta=10) = 1  -> omega components are raw neighbor diffs of P-T
//   voxel contributes & counts  <=> all 27 masks in its 3x3x3 neighborhood == 1
namespace {
constexpr int Bn = 2, Cn = 4, Dn = 64, Hn = 256, Wn = 256;
constexpr long long CH = (long long)Dn * Hn * Wn;
constexpr int GY = 127;            // y-chunks of 2 rows: 2*127 = 254 interior rows
constexpr int NBLK = 4 * GY;       // grid = (127, 4)  [4 = b(2) x z-half(2)]
}

__device__ double       g_psum[NBLK];
__device__ unsigned int g_pcnt[NBLK];

// Block = 512 threads: x = tid&255 (full row), ty = tid>>8 (2 y-rows).
// Marches z through its half-volume; 3-row mask column-products live in
// registers (rzm, rz, rzp) -- only smem traffic is 4 staged mask rows + the
// 27-AND row S per iteration.
__global__ __launch_bounds__(512, 4)
void k_main(const float* __restrict__ P,
            const float* __restrict__ T,
            const float* __restrict__ M) {
    const int tid = threadIdx.x;
    const int x   = tid & 255;
    const int ty  = tid >> 8;                    // 0..1
    const int cy  = blockIdx.x;                  // 0..126
    const int b   = blockIdx.y >> 1;
    const int zc  = blockIdx.y & 1;
    const int y0  = 1 + cy * 2;
    const int y   = y0 + ty;                     // 1..254, always interior
    const int z0  = 1 + zc * 31;
    const int z1  = z0 + 30;                     // 31 z-planes per block

    __shared__ float mrow[4][Wn];                // mask rows y0-1 .. y0+2
    __shared__ float S[2][Wn];                   // 9-product (3z x 3y) per column

    const float* mb = M + (long long)b * CH;
    const float* Pu = P + ((long long)b * Cn + 1) * CH;
    const float* Tu = T + ((long long)b * Cn + 1) * CH;
    const float* Pv = Pu + CH;  const float* Tv = Tu + CH;
    const float* Pw = Pv + CH;  const float* Tw = Tv + CH;

    // Prologue: register column-products for planes z0-1 and z0.
    float rzm, rz;
    {
        const float* pl = mb + (long long)(z0 - 1) * (Hn * Wn);
        #pragma unroll
        for (int i = tid; i < 4 * Wn; i += 512)
            mrow[i >> 8][i & 255] = pl[(y0 - 1 + (i >> 8)) * Wn + (i & 255)];
        __syncthreads();
        rzm = mrow[ty][x] * mrow[ty + 1][x] * mrow[ty + 2][x];
        __syncthreads();

        pl = mb + (long long)z0 * (Hn * Wn);
        #pragma unroll
        for (int i = tid; i < 4 * Wn; i += 512)
            mrow[i >> 8][i & 255] = pl[(y0 - 1 + (i >> 8)) * Wn + (i & 255)];
        __syncthreads();
        rz = mrow[ty][x] * mrow[ty + 1][x] * mrow[ty + 2][x];
        __syncthreads();   // protect mrow before first loop staging
    }

    float fsum = 0.f;
    int   cnt  = 0;

    for (int z = z0; z <= z1; ++z) {
        // Stage mask rows of plane z+1 (all reads are in-bounds: y0-1>=0, y0+2<=255).
        const float* pl = mb + (long long)(z + 1) * (Hn * Wn);
        #pragma unroll
        for (int i = tid; i < 4 * Wn; i += 512)
            mrow[i >> 8][i & 255] = pl[(y0 - 1 + (i >> 8)) * Wn + (i & 255)];
        __syncthreads();

        const float rzp = mrow[ty][x] * mrow[ty + 1][x] * mrow[ty + 2][x];
        S[ty][x] = rzm * rz * rzp;               // 9-neighborhood product, this column
        __syncthreads();

        if (x >= 1 && x <= Wn - 2) {
            const float ok = S[ty][x - 1] * S[ty][x] * S[ty][x + 1];  // 27-AND
            if (ok > 0.f) {
                cnt++;
                const long long i  = ((long long)z * Hn + y) * Wn + x;
                const long long zp = i + (long long)Hn * Wn;
                const long long zm = i - (long long)Hn * Wn;
                const long long yp = i + Wn;
                const long long ym = i - Wn;

                const float ox = ((Pw[yp] - Tw[yp]) - (Pw[ym] - Tw[ym]))
                               - ((Pv[zp] - Tv[zp]) - (Pv[zm] - Tv[zm]));
                const float oy = ((Pu[zp] - Tu[zp]) - (Pu[zm] - Tu[zm]))
                               - ((Pw[i + 1] - Tw[i + 1]) - (Pw[i - 1] - Tw[i - 1]));
                const float oz = ((Pv[i + 1] - Tv[i + 1]) - (Pv[i - 1] - Tv[i - 1]))
                               - ((Pu[yp] - Tu[yp]) - (Pu[ym] - Tu[ym]));

                fsum += sqrtf(ox * ox + oy * oy + oz * oz);
            }
        }
        rzm = rz; rz = rzp;
        // No extra sync needed: next staging write to mrow only happens after
        // all threads pass the sync above in the *next* iteration's stage+sync,
        // and S is rewritten only after everyone re-arrives there too.
    }

    // Block reduction: warp shuffle + 16-warp smem stage, one partial per block.
    #pragma unroll
    for (int off = 16; off; off >>= 1) {
        fsum += __shfl_down_sync(0xffffffffu, fsum, off);
        cnt  += __shfl_down_sync(0xffffffffu, cnt,  off);
    }
    __shared__ float ws[16];
    __shared__ int   wc[16];
    const int wid = tid >> 5, lid = tid & 31;
    if (lid == 0) { ws[wid] = fsum; wc[wid] = cnt; }
    __syncthreads();
    if (wid == 0) {
        fsum = (lid < 16) ? ws[lid] : 0.f;
        cnt  = (lid < 16) ? wc[lid] : 0;
        #pragma unroll
        for (int off = 8; off; off >>= 1) {
            fsum += __shfl_down_sync(0xffffffffu, fsum, off);
            cnt  += __shfl_down_sync(0xffffffffu, cnt,  off);
        }
        if (lid == 0) {
            const int slot = blockIdx.y * GY + blockIdx.x;
            g_psum[slot] = (double)fsum;          // unconditional -> no zero kernel
            g_pcnt[slot] = (unsigned)cnt;
        }
    }
}

__global__ void k_final(float* __restrict__ out) {
    const int tid = threadIdx.x;                  // 512 threads
    double       s = (tid < NBLK) ? g_psum[tid] : 0.0;
    unsigned int c = (tid < NBLK) ? g_pcnt[tid] : 0u;
    #pragma unroll
    for (int off = 16; off; off >>= 1) {
        s += __shfl_down_sync(0xffffffffu, s, off);
        c += __shfl_down_sync(0xffffffffu, c, off);
    }
    __shared__ double   ds[16];
    __shared__ unsigned dc[16];
    const int wid = tid >> 5, lid = tid & 31;
    if (lid == 0) { ds[wid] = s; dc[wid] = c; }
    __syncthreads();
    if (wid == 0) {
        s = (lid < 16) ? ds[lid] : 0.0;
        c = (lid < 16) ? dc[lid] : 0u;
        #pragma unroll
        for (int off = 8; off; off >>= 1) {
            s += __shfl_down_sync(0xffffffffu, s, off);
            c += __shfl_down_sync(0xffffffffu, c, off);
        }
        if (lid == 0) out[0] = (float)(s / (double)c);
    }
}

extern "C" void kernel_launch(void* const* d_in, const int* in_sizes, int n_in,
                              void* d_out, int out_size) {
    const float* P = (const float*)d_in[0];
    const float* T = (const float*)d_in[1];
    const float* M = (const float*)d_in[2];
    float*       O = (float*)d_out;

    k_main<<<dim3(GY, 4), 512>>>(P, T, M);
    k_final<<<1, 512>>>(O);
}